// round 10
// baseline (speedup 1.0000x reference)
#include <cuda_runtime.h>
#include <stdint.h>
#include <math.h>

#define N 4096
#define D 128
#define TM 128
#define TN 128
#define NT (N / TN)
#define NCTA 288

// ---------------------------------------------------------------------------
// device scratch (no allocations allowed)
// ---------------------------------------------------------------------------
__device__ float    g_sq[2][N];
__device__ int      g_t[N];
__device__ unsigned g_apu[4][N];     // monotone-keyed squared-dist row max
__device__ unsigned g_anu[4][N];     // monotone-keyed squared-dist row min
// int8 quantized split: v = 128*h + l, v = rint(2048*x)
__device__ __align__(16) signed char g_i8h[2][N][D];
__device__ __align__(16) signed char g_i8l[2][N][D];

// ---------------------------------------------------------------------------
// helpers (target-agnostic PTX only: sm_80-era mma/ldmatrix/cp.async)
// ---------------------------------------------------------------------------
__device__ __forceinline__ uint32_t smem_u32(const void* p) {
    uint32_t a;
    asm("{ .reg .u64 t; cvta.to.shared.u64 t, %1; cvt.u32.u64 %0, t; }"
        : "=r"(a) : "l"(p));
    return a;
}
__device__ __forceinline__ void cpasync16(uint32_t d, const void* s) {
    asm volatile("cp.async.cg.shared.global [%0], [%1], 16;"
                 :: "r"(d), "l"(s) : "memory");
}
#define CP_COMMIT() asm volatile("cp.async.commit_group;" ::: "memory")
#define CP_WAIT0()  asm volatile("cp.async.wait_group 0;" ::: "memory")

__device__ __forceinline__ void ldsm4(uint32_t addr, uint32_t* r) {
    asm volatile("ldmatrix.sync.aligned.m8n8.x4.shared.b16 {%0,%1,%2,%3}, [%4];"
                 : "=r"(r[0]), "=r"(r[1]), "=r"(r[2]), "=r"(r[3]) : "r"(addr));
}
__device__ __forceinline__ void imma(int* c, const uint32_t* a,
                                     uint32_t b0, uint32_t b1) {
    asm volatile(
        "mma.sync.aligned.m16n8k32.row.col.s32.s8.s8.s32 "
        "{%0,%1,%2,%3}, {%4,%5,%6,%7}, {%8,%9}, {%0,%1,%2,%3};"
        : "+r"(c[0]), "+r"(c[1]), "+r"(c[2]), "+r"(c[3])
        : "r"(a[0]), "r"(a[1]), "r"(a[2]), "r"(a[3]), "r"(b0), "r"(b1));
}
// monotone float<->uint key (order-preserving, incl. negatives)
__device__ __forceinline__ unsigned fkey(float f) {
    unsigned b = __float_as_uint(f);
    return (b & 0x80000000u) ? ~b : (b | 0x80000000u);
}
__device__ __forceinline__ float funkey(unsigned k) {
    unsigned b = (k & 0x80000000u) ? (k & 0x7fffffffu) : ~k;
    return __uint_as_float(b);
}

// ---------------------------------------------------------------------------
// smem layout (bytes). Row = 128 int8 (= 64 "b16"), stride 144B: ldmatrix
// 8-row bases hit offsets 0,16,..,112 mod 128 -> conflict-free.
// ---------------------------------------------------------------------------
#define RS        72                     // row stride in b16 units
#define RB        144                    // row stride bytes
#define A_BYTES   (128 * RB)             // 18432 per matrix
#define SMEM_AH   0
#define SMEM_AL   (SMEM_AH + A_BYTES)
#define SMEM_B    (SMEM_AL + A_BYTES)    // 2 bufs x (h+l)
#define BBUF      (2 * A_BYTES)
#define SMEM_MSQ  (SMEM_B + 2 * BBUF)
#define SMEM_MT   (SMEM_MSQ + 1024)
#define SMEM_RAP  (SMEM_MT + 1024)
#define SMEM_RAN  (SMEM_RAP + 2048)
#define SMEM_TOT  (SMEM_RAN + 2048)

// dist epilogue constants: d = sqa+sqb - 2*(2^-22)*(16384*HH + 128*M)
#define CH (-0.0078125f)         // -2^-7
#define CM (-6.103515625e-5f)    // -2^-14

// ---------------------------------------------------------------------------
// prep: warp-per-row. fp32 norms (shfl-reduced), int8 quant split (coalesced),
// target conversion + keyed-reduction init.
// ---------------------------------------------------------------------------
__device__ __forceinline__ int q11(float x) {
    int v = __float2int_rn(x * 2048.0f);
    return max(-16319, min(16319, v));
}

__global__ void prep2_kernel(const float* __restrict__ m1,
                             const float* __restrict__ m2,
                             const unsigned int* __restrict__ tgt_raw) {
    const int tid = threadIdx.x, lid = tid & 31, wid = tid >> 5;
    const int gw = blockIdx.x * 8 + wid;          // 0..8191 (warp = row)
    const int mat = gw >> 12, row = gw & (N - 1);
    const float* src = (mat ? m2 : m1) + (size_t)row * D;

    float4 v = ((const float4*)src)[lid];
    float s = v.x * v.x + v.y * v.y + v.z * v.z + v.w * v.w;
    #pragma unroll
    for (int m = 16; m; m >>= 1) s += __shfl_xor_sync(0xffffffffu, s, m);
    if (lid == 0) g_sq[mat][row] = s;

    int q0 = q11(v.x), q1 = q11(v.y), q2 = q11(v.z), q3 = q11(v.w);
    int h0 = (q0 + 64) >> 7, h1 = (q1 + 64) >> 7;
    int h2 = (q2 + 64) >> 7, h3 = (q3 + 64) >> 7;
    int l0 = q0 - (h0 << 7), l1 = q1 - (h1 << 7);
    int l2 = q2 - (h2 << 7), l3 = q3 - (h3 << 7);
    uint32_t hw = (uint32_t)(h0 & 255) | ((uint32_t)(h1 & 255) << 8) |
                  ((uint32_t)(h2 & 255) << 16) | ((uint32_t)(h3 & 255) << 24);
    uint32_t lw = (uint32_t)(l0 & 255) | ((uint32_t)(l1 & 255) << 8) |
                  ((uint32_t)(l2 & 255) << 16) | ((uint32_t)(l3 & 255) << 24);
    ((uint32_t*)&g_i8h[mat][row][0])[lid] = hw;
    ((uint32_t*)&g_i8l[mat][row][0])[lid] = lw;

    // targets + reduction init (first 16 blocks cover 4096)
    int t = blockIdx.x * 256 + tid;
    if (t < N) {
        bool is64 = true;
        #pragma unroll
        for (int j = 0; j < 32; j++)
            if (tgt_raw[2 * j + 1] != 0u) is64 = false;
        g_t[t] = is64 ? (int)tgt_raw[2 * t] : (int)tgt_raw[t];
        const unsigned kap = fkey(-1e30f), kan = fkey(1e30f);
        #pragma unroll
        for (int c = 0; c < 4; c++) {
            g_apu[c][t] = kap;
            g_anu[c][t] = kan;
        }
    }
}

// ---------------------------------------------------------------------------
// tile copy: global [128][128]int8 -> smem 144B-stride rows (cp.async)
// 16KB = 1024 x 16B chunks, 256 threads x 4
// ---------------------------------------------------------------------------
__device__ __forceinline__ void copy_tile(uint32_t dst, const signed char* src,
                                          int tid) {
    const uint4* s = (const uint4*)src;
    #pragma unroll
    for (int j = 0; j < 4; j++) {
        int i = tid + j * 256;
        int row = i >> 3, c = i & 7;
        cpasync16(dst + row * RB + c * 16, s + i);
    }
}

// ---------------------------------------------------------------------------
// main fused kernel: same 288-chunk static schedule as the 94.7us version.
// chunks: c<128 -> rt combo (full 32x32, col side feeds tr);
//         else  -> symmetric combos 0/1, upper-triangular tiles, col side
//                  feeds the same combo via transpose.
// ---------------------------------------------------------------------------
__global__ void __launch_bounds__(256, 1)
dist_mma_kernel() {
    extern __shared__ char smem[];
    const uint32_t sb = smem_u32(smem);
    const int tid = threadIdx.x, wid = tid >> 5, lid = tid & 31;

    // ---- work decode ----
    int combo, col_combo, rb, kb_lo, kb_hi;
    {
        int c = blockIdx.x;
        if (c < 128) {
            combo = 2; col_combo = 3;
            rb = c >> 2;
            kb_lo = (c & 3) * 8;
            kb_hi = kb_lo + 8;
        } else {
            int s = c - 128;
            combo = 0;
            if (s >= 80) { combo = 1; s -= 80; }
            col_combo = combo;
            int rbv = 0, jv = 0, s2 = s;
            #pragma unroll 1
            for (int r = 0; r < 32; r++) {
                int nch = 4 - (r >> 3);
                if (s2 < nch) { rbv = r; jv = (r >> 3) + s2; break; }
                s2 -= nch;
            }
            rb = rbv;
            kb_lo = max(rb, jv * 8);
            kb_hi = jv * 8 + 8;
        }
    }
    const int qsi = (combo == 1) ? 1 : 0;
    const int ksi = (combo == 0) ? 0 : 1;

    const int wm = wid & 1;             // M half (64 rows)
    const int wn = wid >> 1;            // N quarter (32 cols)
    const int g4 = lid >> 2, q4 = lid & 3;
    const int lg = lid >> 3, lr = lid & 7;

    float* s_msq = (float*)(smem + SMEM_MSQ);
    int*   s_mt  = (int*)(smem + SMEM_MT);
    float* s_rap = (float*)(smem + SMEM_RAP);
    float* s_ran = (float*)(smem + SMEM_RAN);

    // ---- prologue: A h/l + B(kb_lo) h/l + meta0 ----
    copy_tile(sb + SMEM_AH, &g_i8h[qsi][rb * TM][0], tid);
    copy_tile(sb + SMEM_AL, &g_i8l[qsi][rb * TM][0], tid);
    copy_tile(sb + SMEM_B,           &g_i8h[ksi][kb_lo * TN][0], tid);
    copy_tile(sb + SMEM_B + A_BYTES, &g_i8l[ksi][kb_lo * TN][0], tid);
    if (tid < 32)
        cpasync16(sb + SMEM_MSQ + tid * 16,
                  (const char*)&g_sq[ksi][kb_lo * TN] + tid * 16);
    else if (tid < 64)
        cpasync16(sb + SMEM_MT + (tid - 32) * 16,
                  (const char*)&g_t[kb_lo * TN] + (tid - 32) * 16);
    CP_COMMIT();

    // per-thread row metadata
    float sqa[4][2]; int ta[4][2];
    #pragma unroll
    for (int mf = 0; mf < 4; mf++)
        #pragma unroll
        for (int h = 0; h < 2; h++) {
            int r = rb * TM + wm * 64 + mf * 16 + g4 + h * 8;
            sqa[mf][h] = g_sq[qsi][r];
            ta[mf][h]  = g_t[r];
        }

    float ap[8], an[8];
    #pragma unroll
    for (int s = 0; s < 8; s++) { ap[s] = -1e30f; an[s] = 1e30f; }

    int accH[4][4][4], accM[4][4][4];
    #pragma unroll
    for (int mf = 0; mf < 4; mf++)
        #pragma unroll
        for (int nf = 0; nf < 4; nf++)
            #pragma unroll
            for (int e = 0; e < 4; e++) { accH[mf][nf][e] = 0; accM[mf][nf][e] = 0; }

    // fragment smem byte offsets (lane-only); b16-unit addressing * 2
    const uint32_t aoff = (uint32_t)((wm * 64 + (lg & 1) * 8 + lr) * RS
                                     + (lg >> 1) * 8) * 2;
    const uint32_t boff = (uint32_t)((wn * 32 + (lg >> 1) * 8 + lr) * RS
                                     + (lg & 1) * 8) * 2;

    CP_WAIT0();
    __syncthreads();

    for (int kb = kb_lo; kb < kb_hi; kb++) {
        const int cb = (kb - kb_lo) & 1;

        if (kb + 1 < kb_hi) {
            const int nb = 1 - cb;
            copy_tile(sb + SMEM_B + nb * BBUF,
                      &g_i8h[ksi][(kb + 1) * TN][0], tid);
            copy_tile(sb + SMEM_B + nb * BBUF + A_BYTES,
                      &g_i8l[ksi][(kb + 1) * TN][0], tid);
            if (tid < 32)
                cpasync16(sb + SMEM_MSQ + nb * 512 + tid * 16,
                          (const char*)&g_sq[ksi][(kb + 1) * TN] + tid * 16);
            else if (tid < 64)
                cpasync16(sb + SMEM_MT + nb * 512 + (tid - 32) * 16,
                          (const char*)&g_t[(kb + 1) * TN] + (tid - 32) * 16);
        }
        CP_COMMIT();

        const uint32_t bH = sb + SMEM_B + cb * BBUF;
        const uint32_t bL = bH + A_BYTES;

        // 4 k-steps of K=32 int8 (16 b16 cols each)
        for (int ks = 0; ks < 4; ks++) {
            const uint32_t kadd = (uint32_t)ks * 32;   // 16 b16 * 2B
            uint32_t Ah[4][4], Al[4][4];
            #pragma unroll
            for (int mf = 0; mf < 4; mf++) {
                const uint32_t off = aoff + (uint32_t)(mf * 16 * RS) * 2 + kadd;
                ldsm4(sb + SMEM_AH + off, Ah[mf]);
                ldsm4(sb + SMEM_AL + off, Al[mf]);
            }
            uint32_t Bh[2][4], Bl[2][4];
            #pragma unroll
            for (int ph = 0; ph < 2; ph++) {
                const uint32_t off = boff + (uint32_t)(ph * 16 * RS) * 2 + kadd;
                ldsm4(bH + off, Bh[ph]);
                ldsm4(bL + off, Bl[ph]);
            }
            #pragma unroll
            for (int mf = 0; mf < 4; mf++)
                #pragma unroll
                for (int nf = 0; nf < 4; nf++) {
                    const int ph = nf >> 1, sub = nf & 1;
                    imma(accH[mf][nf], Ah[mf], Bh[ph][2 * sub], Bh[ph][2 * sub + 1]);
                    imma(accM[mf][nf], Ah[mf], Bl[ph][2 * sub], Bl[ph][2 * sub + 1]);
                    imma(accM[mf][nf], Al[mf], Bh[ph][2 * sub], Bh[ph][2 * sub + 1]);
                }
        }

        // ---- epilogue: row-side accumulate + col-side (transpose) ----
        const bool do_col = (combo == 2) || (kb != rb);
        float apc[4][2], anc[4][2];
        #pragma unroll
        for (int nf = 0; nf < 4; nf++)
            #pragma unroll
            for (int par = 0; par < 2; par++) {
                apc[nf][par] = -1e30f;
                anc[nf][par] = 1e30f;
            }

        #pragma unroll
        for (int nf = 0; nf < 4; nf++) {
            const int c0 = wn * 32 + nf * 8 + 2 * q4;
            const float sqb0 = s_msq[cb * 128 + c0];
            const float sqb1 = s_msq[cb * 128 + c0 + 1];
            const int   tb0  = s_mt[cb * 128 + c0];
            const int   tb1  = s_mt[cb * 128 + c0 + 1];
            #pragma unroll
            for (int mf = 0; mf < 4; mf++) {
                #pragma unroll
                for (int h = 0; h < 2; h++) {
                    const int s = mf * 2 + h;
                    float v0 = sqa[mf][h] + sqb0;
                    v0 = fmaf((float)accH[mf][nf][2 * h], CH, v0);
                    v0 = fmaf((float)accM[mf][nf][2 * h], CM, v0);
                    float v1 = sqa[mf][h] + sqb1;
                    v1 = fmaf((float)accH[mf][nf][2 * h + 1], CH, v1);
                    v1 = fmaf((float)accM[mf][nf][2 * h + 1], CM, v1);
                    if (ta[mf][h] == tb0) {
                        ap[s] = fmaxf(ap[s], v0);
                        apc[nf][0] = fmaxf(apc[nf][0], v0);
                    } else {
                        an[s] = fminf(an[s], v0);
                        anc[nf][0] = fminf(anc[nf][0], v0);
                    }
                    if (ta[mf][h] == tb1) {
                        ap[s] = fmaxf(ap[s], v1);
                        apc[nf][1] = fmaxf(apc[nf][1], v1);
                    } else {
                        an[s] = fminf(an[s], v1);
                        anc[nf][1] = fminf(anc[nf][1], v1);
                    }
                    accH[mf][nf][2 * h] = 0;     accM[mf][nf][2 * h] = 0;
                    accH[mf][nf][2 * h + 1] = 0; accM[mf][nf][2 * h + 1] = 0;
                }
            }
        }

        if (do_col) {
            #pragma unroll
            for (int nf = 0; nf < 4; nf++)
                #pragma unroll
                for (int par = 0; par < 2; par++) {
                    #pragma unroll
                    for (int m = 4; m < 32; m <<= 1) {
                        apc[nf][par] = fmaxf(apc[nf][par],
                            __shfl_xor_sync(0xffffffffu, apc[nf][par], m));
                        anc[nf][par] = fminf(anc[nf][par],
                            __shfl_xor_sync(0xffffffffu, anc[nf][par], m));
                    }
                }
            if (lid < 4) {
                #pragma unroll
                for (int nf = 0; nf < 4; nf++)
                    #pragma unroll
                    for (int par = 0; par < 2; par++) {
                        int j = kb * TN + wn * 32 + nf * 8 + 2 * lid + par;
                        atomicMax(&g_apu[col_combo][j], fkey(apc[nf][par]));
                        atomicMin(&g_anu[col_combo][j], fkey(anc[nf][par]));
                    }
            }
        }

        CP_WAIT0();
        __syncthreads();
    }

    // ---- row-side final reduce + atomics ----
    #pragma unroll
    for (int s = 0; s < 8; s++) {
        #pragma unroll
        for (int m = 1; m < 4; m <<= 1) {
            ap[s] = fmaxf(ap[s], __shfl_xor_sync(0xffffffffu, ap[s], m));
            an[s] = fminf(an[s], __shfl_xor_sync(0xffffffffu, an[s], m));
        }
    }
    if (q4 == 0) {
        #pragma unroll
        for (int mf = 0; mf < 4; mf++)
            #pragma unroll
            for (int h = 0; h < 2; h++) {
                int row = wm * 64 + mf * 16 + g4 + h * 8;
                s_rap[wn * 128 + row] = ap[mf * 2 + h];
                s_ran[wn * 128 + row] = an[mf * 2 + h];
            }
    }
    __syncthreads();
    if (tid < 128) {
        float p = s_rap[tid], q = s_ran[tid];
        #pragma unroll
        for (int w = 1; w < 4; w++) {
            p = fmaxf(p, s_rap[w * 128 + tid]);
            q = fminf(q, s_ran[w * 128 + tid]);
        }
        atomicMax(&g_apu[combo][rb * TM + tid], fkey(p));
        atomicMin(&g_anu[combo][rb * TM + tid], fkey(q));
    }
}

// ---------------------------------------------------------------------------
// finalize (single block, 1024 threads): sqrt + margin loss + precision
// pairs: (ap1,an1)(ap2,an2)(ap3,an3)(ap4,an4)(ap3,an1)(ap4,an2)
// ---------------------------------------------------------------------------
__global__ void finalize_kernel(float* __restrict__ out, int out_size) {
    __shared__ float sl[32];
    __shared__ float sp[32];
    const int tid = threadIdx.x, lid = tid & 31, wid = tid >> 5;
    const int pi[6] = {0, 1, 2, 3, 2, 3};
    const int ni[6] = {0, 1, 2, 3, 0, 1};
    float lsum = 0.f, psum = 0.f;
    #pragma unroll
    for (int it = 0; it < 4; it++) {
        const int i = tid + it * 1024;
        float A[4], B[4];
        #pragma unroll
        for (int c = 0; c < 4; c++) {
            A[c] = sqrtf(fmaxf(funkey(g_apu[c][i]), 1e-12f));
            B[c] = sqrtf(fmaxf(funkey(g_anu[c][i]), 1e-12f));
        }
        #pragma unroll
        for (int j = 0; j < 6; j++) {
            float apv = A[pi[j]], anv = B[ni[j]];
            lsum += fmaxf(apv - anv + 0.3f, 0.f);
            psum += (anv > apv) ? 1.f : 0.f;
        }
    }
    #pragma unroll
    for (int m = 16; m; m >>= 1) {
        lsum += __shfl_xor_sync(0xffffffffu, lsum, m);
        psum += __shfl_xor_sync(0xffffffffu, psum, m);
    }
    if (lid == 0) { sl[wid] = lsum; sp[wid] = psum; }
    __syncthreads();
    if (wid == 0) {
        float l = sl[lid], p = sp[lid];
        #pragma unroll
        for (int m = 16; m; m >>= 1) {
            l += __shfl_xor_sync(0xffffffffu, l, m);
            p += __shfl_xor_sync(0xffffffffu, p, m);
        }
        if (lid == 0) {
            const float inv = 1.f / (6.f * (float)N);
            if (out_size > 0) out[0] = l * inv;
            if (out_size > 1) out[1] = p * inv;
        }
    }
}

// ---------------------------------------------------------------------------
extern "C" void kernel_launch(void* const* d_in, const int* in_sizes, int n_in,
                              void* d_out, int out_size) {
    const float* m1 = (const float*)d_in[0];
    const float* m2 = (const float*)d_in[1];
    const unsigned int* tgt = (const unsigned int*)d_in[2];
    float* out = (float*)d_out;

    cudaFuncSetAttribute(dist_mma_kernel,
                         cudaFuncAttributeMaxDynamicSharedMemorySize, SMEM_TOT);

    prep2_kernel<<<1024, 256>>>(m1, m2, tgt);
    dist_mma_kernel<<<NCTA, 256, SMEM_TOT>>>();
    finalize_kernel<<<1, 1024>>>(out, out_size);
}

// round 11
// speedup vs baseline: 1.5680x; 1.5680x over previous
#include <cuda_runtime.h>
#include <cuda_bf16.h>
#include <stdint.h>
#include <math.h>

#define N 4096
#define D 128
#define TM 128
#define TN 128
#define NT (N / TN)
#define NCTA 288

// ---------------------------------------------------------------------------
// device scratch (no allocations allowed)
// ---------------------------------------------------------------------------
__device__ float    g_sq[2][N];
__device__ int      g_t[N];
__device__ unsigned g_apu[4][N];     // monotone-keyed squared-dist row max
__device__ unsigned g_anu[4][N];     // monotone-keyed squared-dist row min
__device__ __align__(16) __nv_bfloat16 g_bfh[2][N][D];
__device__ __align__(16) __nv_bfloat16 g_bfl[2][N][D];

// ---------------------------------------------------------------------------
// helpers (target-agnostic PTX only: sm_80-era mma/ldmatrix/cp.async)
// ---------------------------------------------------------------------------
__device__ __forceinline__ uint32_t smem_u32(const void* p) {
    uint32_t a;
    asm("{ .reg .u64 t; cvta.to.shared.u64 t, %1; cvt.u32.u64 %0, t; }"
        : "=r"(a) : "l"(p));
    return a;
}
__device__ __forceinline__ void cpasync16(uint32_t d, const void* s) {
    asm volatile("cp.async.cg.shared.global [%0], [%1], 16;"
                 :: "r"(d), "l"(s) : "memory");
}
#define CP_COMMIT() asm volatile("cp.async.commit_group;" ::: "memory")
#define CP_WAIT0()  asm volatile("cp.async.wait_group 0;" ::: "memory")

__device__ __forceinline__ void ldsm4(uint32_t addr, uint32_t* r) {
    asm volatile("ldmatrix.sync.aligned.m8n8.x4.shared.b16 {%0,%1,%2,%3}, [%4];"
                 : "=r"(r[0]), "=r"(r[1]), "=r"(r[2]), "=r"(r[3]) : "r"(addr));
}
__device__ __forceinline__ void mma_bf16(float* c, const uint32_t* a,
                                         uint32_t b0, uint32_t b1) {
    asm volatile(
        "mma.sync.aligned.m16n8k16.row.col.f32.bf16.bf16.f32 "
        "{%0,%1,%2,%3}, {%4,%5,%6,%7}, {%8,%9}, {%0,%1,%2,%3};"
        : "+f"(c[0]), "+f"(c[1]), "+f"(c[2]), "+f"(c[3])
        : "r"(a[0]), "r"(a[1]), "r"(a[2]), "r"(a[3]), "r"(b0), "r"(b1));
}
// monotone float<->uint key (order-preserving, incl. negatives)
__device__ __forceinline__ unsigned fkey(float f) {
    unsigned b = __float_as_uint(f);
    return (b & 0x80000000u) ? ~b : (b | 0x80000000u);
}
__device__ __forceinline__ float funkey(unsigned k) {
    unsigned b = (k & 0x80000000u) ? (k & 0x7fffffffu) : ~k;
    return __uint_as_float(b);
}

// ---------------------------------------------------------------------------
// smem layout (bytes). Row stride 272B kills ldmatrix bank conflicts.
// ---------------------------------------------------------------------------
#define RS        136
#define RB        272
#define A_BYTES   (128 * RB)             // 34816 per (hi|lo)
#define SMEM_AH   0
#define SMEM_AL   (SMEM_AH + A_BYTES)
#define SMEM_B    (SMEM_AL + A_BYTES)    // 2 bufs x (hi+lo)
#define BBUF      (2 * A_BYTES)
#define SMEM_MSQ  (SMEM_B + 2 * BBUF)
#define SMEM_MT   (SMEM_MSQ + 1024)
#define SMEM_RAP  (SMEM_MT + 1024)
#define SMEM_RAN  (SMEM_RAP + 2048)
#define SMEM_TOT  (SMEM_RAN + 2048)

// ---------------------------------------------------------------------------
// prep: warp-per-row. norms (shfl-reduced), bf16 hi/lo split (coalesced),
// target conversion + keyed-reduction init.
// ---------------------------------------------------------------------------
__device__ __forceinline__ void split2(float x0, float x1, uint32_t& h, uint32_t& l) {
    __nv_bfloat162 hh = __floats2bfloat162_rn(x0, x1);
    float r0 = x0 - __bfloat162float(hh.x);
    float r1 = x1 - __bfloat162float(hh.y);
    __nv_bfloat162 ll = __floats2bfloat162_rn(r0, r1);
    h = *reinterpret_cast<uint32_t*>(&hh);
    l = *reinterpret_cast<uint32_t*>(&ll);
}

__global__ void prep2_kernel(const float* __restrict__ m1,
                             const float* __restrict__ m2,
                             const unsigned int* __restrict__ tgt_raw) {
    const int tid = threadIdx.x, lid = tid & 31, wid = tid >> 5;
    const int gw = blockIdx.x * 8 + wid;          // 0..8191 (warp = row)
    const int mat = gw >> 12, row = gw & (N - 1);
    const float* src = (mat ? m2 : m1) + (size_t)row * D;

    float4 v = ((const float4*)src)[lid];
    float s = v.x * v.x + v.y * v.y + v.z * v.z + v.w * v.w;
    #pragma unroll
    for (int m = 16; m; m >>= 1) s += __shfl_xor_sync(0xffffffffu, s, m);
    if (lid == 0) g_sq[mat][row] = s;

    uint32_t h0, h1, l0, l1;
    split2(v.x, v.y, h0, l0);
    split2(v.z, v.w, h1, l1);
    ((uint2*)&g_bfh[mat][row][0])[lid] = make_uint2(h0, h1);
    ((uint2*)&g_bfl[mat][row][0])[lid] = make_uint2(l0, l1);

    // targets + reduction init (first 16 blocks cover 4096)
    int t = blockIdx.x * 256 + tid;
    if (t < N) {
        bool is64 = true;
        #pragma unroll
        for (int j = 0; j < 32; j++)
            if (tgt_raw[2 * j + 1] != 0u) is64 = false;
        g_t[t] = is64 ? (int)tgt_raw[2 * t] : (int)tgt_raw[t];
        const unsigned kap = fkey(-1e30f), kan = fkey(1e30f);
        #pragma unroll
        for (int c = 0; c < 4; c++) {
            g_apu[c][t] = kap;
            g_anu[c][t] = kan;
        }
    }
}

// ---------------------------------------------------------------------------
// tile copy: global row-major [128][128]bf16 -> smem padded rows (cp.async)
// ---------------------------------------------------------------------------
__device__ __forceinline__ void copy_tile(uint32_t dst, const __nv_bfloat16* src,
                                          int tid) {
    const uint4* s = (const uint4*)src;
    #pragma unroll
    for (int j = 0; j < 8; j++) {
        int i = tid + j * 256;
        int row = i >> 4, c = i & 15;
        cpasync16(dst + row * RB + c * 16, s + i);
    }
}

// ---------------------------------------------------------------------------
// main fused kernel, LPT-ordered static work list.
//   c in [0,128)    : rt combo (8-tile chunks; col side feeds tr)
//   c in [128,288)  : symmetric combos 0/1 upper-triangular, ordered
//                     off-diagonal full 8-tile chunks first, then diagonal
//                     chunks (size 8-(rb&7)) last -> big-to-small draining.
// ---------------------------------------------------------------------------
__global__ void __launch_bounds__(256, 1)
dist_mma_kernel() {
    extern __shared__ char smem[];
    const uint32_t sb = smem_u32(smem);
    const int tid = threadIdx.x, wid = tid >> 5, lid = tid & 31;

    // ---- work decode ----
    int combo, col_combo, rb, kb_lo, kb_hi;
    {
        int c = blockIdx.x;
        if (c < 128) {
            combo = 2; col_combo = 3;
            rb = c >> 2;
            kb_lo = (c & 3) * 8;
            kb_hi = kb_lo + 8;
        } else {
            int s = c - 128;
            combo = 0;
            if (s >= 80) { combo = 1; s -= 80; }
            col_combo = combo;
            if (s < 48) {
                // off-diagonal full chunks (j > rb>>3), all size 8
                int j;
                if (s < 24)      { rb = s / 3;            j = 1 + s % 3; }
                else if (s < 40) { int t = s - 24; rb = 8 + t / 2;  j = 2 + (t & 1); }
                else             { int t = s - 40; rb = 16 + t;     j = 3; }
                kb_lo = j * 8;
                kb_hi = kb_lo + 8;
            } else {
                // diagonal chunks, size 8-(rb&7), issued last (LPT)
                rb = s - 48;
                kb_lo = rb;
                kb_hi = (rb >> 3) * 8 + 8;
            }
        }
    }
    const int qsi = (combo == 1) ? 1 : 0;
    const int ksi = (combo == 0) ? 0 : 1;

    const int wm = wid & 1;             // M half (64 rows)
    const int wn = wid >> 1;            // N quarter (32 cols)
    const int g4 = lid >> 2, q4 = lid & 3;
    const int lg = lid >> 3, lr = lid & 7;

    float* s_msq = (float*)(smem + SMEM_MSQ);
    int*   s_mt  = (int*)(smem + SMEM_MT);
    float* s_rap = (float*)(smem + SMEM_RAP);
    float* s_ran = (float*)(smem + SMEM_RAN);

    // ---- prologue: A hi/lo + B(kb_lo) hi/lo + meta0 ----
    copy_tile(sb + SMEM_AH, &g_bfh[qsi][rb * TM][0], tid);
    copy_tile(sb + SMEM_AL, &g_bfl[qsi][rb * TM][0], tid);
    copy_tile(sb + SMEM_B,           &g_bfh[ksi][kb_lo * TN][0], tid);
    copy_tile(sb + SMEM_B + A_BYTES, &g_bfl[ksi][kb_lo * TN][0], tid);
    if (tid < 32)
        cpasync16(sb + SMEM_MSQ + tid * 16,
                  (const char*)&g_sq[ksi][kb_lo * TN] + tid * 16);
    else if (tid < 64)
        cpasync16(sb + SMEM_MT + (tid - 32) * 16,
                  (const char*)&g_t[kb_lo * TN] + (tid - 32) * 16);
    CP_COMMIT();

    // per-thread row metadata
    float sqa[4][2]; int ta[4][2];
    #pragma unroll
    for (int mf = 0; mf < 4; mf++)
        #pragma unroll
        for (int h = 0; h < 2; h++) {
            int r = rb * TM + wm * 64 + mf * 16 + g4 + h * 8;
            sqa[mf][h] = g_sq[qsi][r];
            ta[mf][h]  = g_t[r];
        }

    float ap[8], an[8];
    #pragma unroll
    for (int s = 0; s < 8; s++) { ap[s] = -1e30f; an[s] = 1e30f; }

    float acc[4][4][4];
    #pragma unroll
    for (int mf = 0; mf < 4; mf++)
        #pragma unroll
        for (int nf = 0; nf < 4; nf++)
            #pragma unroll
            for (int e = 0; e < 4; e++) acc[mf][nf][e] = 0.f;

    CP_WAIT0();
    __syncthreads();

    for (int kb = kb_lo; kb < kb_hi; kb++) {
        const int cb = (kb - kb_lo) & 1;

        if (kb + 1 < kb_hi) {
            const int nb = 1 - cb;
            copy_tile(sb + SMEM_B + nb * BBUF,
                      &g_bfh[ksi][(kb + 1) * TN][0], tid);
            copy_tile(sb + SMEM_B + nb * BBUF + A_BYTES,
                      &g_bfl[ksi][(kb + 1) * TN][0], tid);
            if (tid < 32)
                cpasync16(sb + SMEM_MSQ + nb * 512 + tid * 16,
                          (const char*)&g_sq[ksi][(kb + 1) * TN] + tid * 16);
            else if (tid < 64)
                cpasync16(sb + SMEM_MT + nb * 512 + (tid - 32) * 16,
                          (const char*)&g_t[(kb + 1) * TN] + (tid - 32) * 16);
        }
        CP_COMMIT();

        const uint32_t bH = sb + SMEM_B + cb * BBUF;
        const uint32_t bL = bH + A_BYTES;

        for (int ks = 0; ks < 8; ks++) {
            uint32_t Ah[4][4], Al[4][4];
            #pragma unroll
            for (int mf = 0; mf < 4; mf++) {
                int mrow = wm * 64 + mf * 16 + (lg & 1) * 8 + lr;
                int kcol = ks * 16 + (lg >> 1) * 8;
                uint32_t off = (uint32_t)(mrow * RS + kcol) * 2;
                ldsm4(sb + SMEM_AH + off, Ah[mf]);
                ldsm4(sb + SMEM_AL + off, Al[mf]);
            }
            uint32_t Bh[2][4], Bl[2][4];
            #pragma unroll
            for (int ph = 0; ph < 2; ph++) {
                int nrow = wn * 32 + ph * 16 + (lg >> 1) * 8 + lr;
                int kcol = ks * 16 + (lg & 1) * 8;
                uint32_t off = (uint32_t)(nrow * RS + kcol) * 2;
                ldsm4(bH + off, Bh[ph]);
                ldsm4(bL + off, Bl[ph]);
            }
            #pragma unroll
            for (int mf = 0; mf < 4; mf++)
                #pragma unroll
                for (int nf = 0; nf < 4; nf++) {
                    const int ph = nf >> 1, sub = nf & 1;
                    mma_bf16(acc[mf][nf], Ah[mf], Bh[ph][2 * sub], Bh[ph][2 * sub + 1]);
                    mma_bf16(acc[mf][nf], Ah[mf], Bl[ph][2 * sub], Bl[ph][2 * sub + 1]);
                    mma_bf16(acc[mf][nf], Al[mf], Bh[ph][2 * sub], Bh[ph][2 * sub + 1]);
                }
        }

        // ---- epilogue: row-side accumulate + col-side (transpose) ----
        const bool do_col = (combo == 2) || (kb != rb);
        float apc[4][2], anc[4][2];
        #pragma unroll
        for (int nf = 0; nf < 4; nf++)
            #pragma unroll
            for (int par = 0; par < 2; par++) {
                apc[nf][par] = -1e30f;
                anc[nf][par] = 1e30f;
            }

        #pragma unroll
        for (int nf = 0; nf < 4; nf++) {
            const int c0 = wn * 32 + nf * 8 + 2 * q4;
            const float sqb0 = s_msq[cb * 128 + c0];
            const float sqb1 = s_msq[cb * 128 + c0 + 1];
            const int   tb0  = s_mt[cb * 128 + c0];
            const int   tb1  = s_mt[cb * 128 + c0 + 1];
            #pragma unroll
            for (int mf = 0; mf < 4; mf++) {
                #pragma unroll
                for (int h = 0; h < 2; h++) {
                    const int s = mf * 2 + h;
                    float v0 = fmaf(acc[mf][nf][2 * h],     -2.f, sqa[mf][h] + sqb0);
                    float v1 = fmaf(acc[mf][nf][2 * h + 1], -2.f, sqa[mf][h] + sqb1);
                    if (ta[mf][h] == tb0) {
                        ap[s] = fmaxf(ap[s], v0);
                        apc[nf][0] = fmaxf(apc[nf][0], v0);
                    } else {
                        an[s] = fminf(an[s], v0);
                        anc[nf][0] = fminf(anc[nf][0], v0);
                    }
                    if (ta[mf][h] == tb1) {
                        ap[s] = fmaxf(ap[s], v1);
                        apc[nf][1] = fmaxf(apc[nf][1], v1);
                    } else {
                        an[s] = fminf(an[s], v1);
                        anc[nf][1] = fminf(anc[nf][1], v1);
                    }
                    acc[mf][nf][2 * h] = 0.f;
                    acc[mf][nf][2 * h + 1] = 0.f;
                }
            }
        }

        if (do_col) {
            #pragma unroll
            for (int nf = 0; nf < 4; nf++)
                #pragma unroll
                for (int par = 0; par < 2; par++) {
                    #pragma unroll
                    for (int m = 4; m < 32; m <<= 1) {
                        apc[nf][par] = fmaxf(apc[nf][par],
                            __shfl_xor_sync(0xffffffffu, apc[nf][par], m));
                        anc[nf][par] = fminf(anc[nf][par],
                            __shfl_xor_sync(0xffffffffu, anc[nf][par], m));
                    }
                }
            if (lid < 4) {
                #pragma unroll
                for (int nf = 0; nf < 4; nf++)
                    #pragma unroll
                    for (int par = 0; par < 2; par++) {
                        int j = kb * TN + wn * 32 + nf * 8 + 2 * lid + par;
                        atomicMax(&g_apu[col_combo][j], fkey(apc[nf][par]));
                        atomicMin(&g_anu[col_combo][j], fkey(anc[nf][par]));
                    }
            }
        }

        CP_WAIT0();
        __syncthreads();
    }

    // ---- row-side final reduce + atomics ----
    #pragma unroll
    for (int s = 0; s < 8; s++) {
        #pragma unroll
        for (int m = 1; m < 4; m <<= 1) {
            ap[s] = fmaxf(ap[s], __shfl_xor_sync(0xffffffffu, ap[s], m));
            an[s] = fminf(an[s], __shfl_xor_sync(0xffffffffu, an[s], m));
        }
    }
    if (q4 == 0) {
        #pragma unroll
        for (int mf = 0; mf < 4; mf++)
            #pragma unroll
            for (int h = 0; h < 2; h++) {
                int row = wm * 64 + mf * 16 + g4 + h * 8;
                s_rap[wn * 128 + row] = ap[mf * 2 + h];
                s_ran[wn * 128 + row] = an[mf * 2 + h];
            }
    }
    __syncthreads();
    if (tid < 128) {
        float p = s_rap[tid], q = s_ran[tid];
        #pragma unroll
        for (int w = 1; w < 4; w++) {
            p = fmaxf(p, s_rap[w * 128 + tid]);
            q = fminf(q, s_ran[w * 128 + tid]);
        }
        atomicMax(&g_apu[combo][rb * TM + tid], fkey(p));
        atomicMin(&g_anu[combo][rb * TM + tid], fkey(q));
    }
}

// ---------------------------------------------------------------------------
// finalize (single block, 1024 threads): sqrt + margin loss + precision
// pairs: (ap1,an1)(ap2,an2)(ap3,an3)(ap4,an4)(ap3,an1)(ap4,an2)
// ---------------------------------------------------------------------------
__global__ void finalize_kernel(float* __restrict__ out, int out_size) {
    __shared__ float sl[32];
    __shared__ float sp[32];
    const int tid = threadIdx.x, lid = tid & 31, wid = tid >> 5;
    const int pi[6] = {0, 1, 2, 3, 2, 3};
    const int ni[6] = {0, 1, 2, 3, 0, 1};
    float lsum = 0.f, psum = 0.f;
    #pragma unroll
    for (int it = 0; it < 4; it++) {
        const int i = tid + it * 1024;
        float A[4], B[4];
        #pragma unroll
        for (int c = 0; c < 4; c++) {
            A[c] = sqrtf(fmaxf(funkey(g_apu[c][i]), 1e-12f));
            B[c] = sqrtf(fmaxf(funkey(g_anu[c][i]), 1e-12f));
        }
        #pragma unroll
        for (int j = 0; j < 6; j++) {
            float apv = A[pi[j]], anv = B[ni[j]];
            lsum += fmaxf(apv - anv + 0.3f, 0.f);
            psum += (anv > apv) ? 1.f : 0.f;
        }
    }
    #pragma unroll
    for (int m = 16; m; m >>= 1) {
        lsum += __shfl_xor_sync(0xffffffffu, lsum, m);
        psum += __shfl_xor_sync(0xffffffffu, psum, m);
    }
    if (lid == 0) { sl[wid] = lsum; sp[wid] = psum; }
    __syncthreads();
    if (wid == 0) {
        float l = sl[lid], p = sp[lid];
        #pragma unroll
        for (int m = 16; m; m >>= 1) {
            l += __shfl_xor_sync(0xffffffffu, l, m);
            p += __shfl_xor_sync(0xffffffffu, p, m);
        }
        if (lid == 0) {
            const float inv = 1.f / (6.f * (float)N);
            if (out_size > 0) out[0] = l * inv;
            if (out_size > 1) out[1] = p * inv;
        }
    }
}

// ---------------------------------------------------------------------------
extern "C" void kernel_launch(void* const* d_in, const int* in_sizes, int n_in,
                              void* d_out, int out_size) {
    const float* m1 = (const float*)d_in[0];
    const float* m2 = (const float*)d_in[1];
    const unsigned int* tgt = (const unsigned int*)d_in[2];
    float* out = (float*)d_out;

    cudaFuncSetAttribute(dist_mma_kernel,
                         cudaFuncAttributeMaxDynamicSharedMemorySize, SMEM_TOT);

    prep2_kernel<<<1024, 256>>>(m1, m2, tgt);
    dist_mma_kernel<<<NCTA, 256, SMEM_TOT>>>();
    finalize_kernel<<<1, 1024>>>(out, out_size);
}

// round 13
// speedup vs baseline: 2.4773x; 1.5799x over previous
#include <cuda_runtime.h>
#include <cuda_bf16.h>
#include <stdint.h>
#include <math.h>

#define N 4096
#define D 128
#define TM 128
#define TN 128
#define NT (N / TN)
#define NCTA 288

// ---------------------------------------------------------------------------
// device scratch (no allocations allowed)
// ---------------------------------------------------------------------------
__device__ float    g_sq[2][N];
__device__ int      g_t[N];
__device__ unsigned g_apu[4][N];     // monotone-keyed squared-dist row max
__device__ unsigned g_anu[4][N];     // monotone-keyed squared-dist row min
__device__ float    g_part[16][2];
__device__ __align__(16) __nv_bfloat16 g_bfh[2][N][D];
__device__ __align__(16) __nv_bfloat16 g_bfl[2][N][D];

// ---------------------------------------------------------------------------
// helpers (target-agnostic PTX only: sm_80-era mma/ldmatrix/cp.async)
// ---------------------------------------------------------------------------
__device__ __forceinline__ uint32_t smem_u32(const void* p) {
    uint32_t a;
    asm("{ .reg .u64 t; cvta.to.shared.u64 t, %1; cvt.u32.u64 %0, t; }"
        : "=r"(a) : "l"(p));
    return a;
}
__device__ __forceinline__ void cpasync16(uint32_t d, const void* s) {
    asm volatile("cp.async.cg.shared.global [%0], [%1], 16;"
                 :: "r"(d), "l"(s) : "memory");
}
#define CP_COMMIT() asm volatile("cp.async.commit_group;" ::: "memory")
#define CP_WAIT0()  asm volatile("cp.async.wait_group 0;" ::: "memory")

__device__ __forceinline__ void ldsm4(uint32_t addr, uint32_t* r) {
    asm volatile("ldmatrix.sync.aligned.m8n8.x4.shared.b16 {%0,%1,%2,%3}, [%4];"
                 : "=r"(r[0]), "=r"(r[1]), "=r"(r[2]), "=r"(r[3]) : "r"(addr));
}
__device__ __forceinline__ void mma_bf16(float* c, const uint32_t* a,
                                         uint32_t b0, uint32_t b1) {
    asm volatile(
        "mma.sync.aligned.m16n8k16.row.col.f32.bf16.bf16.f32 "
        "{%0,%1,%2,%3}, {%4,%5,%6,%7}, {%8,%9}, {%0,%1,%2,%3};"
        : "+f"(c[0]), "+f"(c[1]), "+f"(c[2]), "+f"(c[3])
        : "r"(a[0]), "r"(a[1]), "r"(a[2]), "r"(a[3]), "r"(b0), "r"(b1));
}
// monotone float<->uint key (order-preserving, incl. negatives)
__device__ __forceinline__ unsigned fkey(float f) {
    unsigned b = __float_as_uint(f);
    return (b & 0x80000000u) ? ~b : (b | 0x80000000u);
}
__device__ __forceinline__ float funkey(unsigned k) {
    unsigned b = (k & 0x80000000u) ? (k & 0x7fffffffu) : ~k;
    return __uint_as_float(b);
}

// ---------------------------------------------------------------------------
// smem layout (bytes). Row stride 272B kills ldmatrix bank conflicts.
// ---------------------------------------------------------------------------
#define RS        136
#define RB        272
#define A_BYTES   (128 * RB)             // 34816 per (hi|lo)
#define SMEM_AH   0
#define SMEM_AL   (SMEM_AH + A_BYTES)
#define SMEM_B    (SMEM_AL + A_BYTES)    // 2 bufs x (hi+lo)
#define BBUF      (2 * A_BYTES)
#define SMEM_MSQ  (SMEM_B + 2 * BBUF)
#define SMEM_MT   (SMEM_MSQ + 1024)
#define SMEM_RAP  (SMEM_MT + 1024)
#define SMEM_RAN  (SMEM_RAP + 2048)
#define SMEM_TOT  (SMEM_RAN + 2048)

// ---------------------------------------------------------------------------
// prep: warp-per-row. norms (shfl-reduced), bf16 hi/lo split (coalesced),
// target conversion + keyed-reduction init.
// ---------------------------------------------------------------------------
__device__ __forceinline__ void split2(float x0, float x1, uint32_t& h, uint32_t& l) {
    __nv_bfloat162 hh = __floats2bfloat162_rn(x0, x1);
    float r0 = x0 - __bfloat162float(hh.x);
    float r1 = x1 - __bfloat162float(hh.y);
    __nv_bfloat162 ll = __floats2bfloat162_rn(r0, r1);
    h = *reinterpret_cast<uint32_t*>(&hh);
    l = *reinterpret_cast<uint32_t*>(&ll);
}

__global__ void prep2_kernel(const float* __restrict__ m1,
                             const float* __restrict__ m2,
                             const unsigned int* __restrict__ tgt_raw) {
    const int tid = threadIdx.x, lid = tid & 31, wid = tid >> 5;
    const int gw = blockIdx.x * 8 + wid;          // 0..8191 (warp = row)
    const int mat = gw >> 12, row = gw & (N - 1);
    const float* src = (mat ? m2 : m1) + (size_t)row * D;

    float4 v = ((const float4*)src)[lid];
    float s = v.x * v.x + v.y * v.y + v.z * v.z + v.w * v.w;
    #pragma unroll
    for (int m = 16; m; m >>= 1) s += __shfl_xor_sync(0xffffffffu, s, m);
    if (lid == 0) g_sq[mat][row] = s;

    uint32_t h0, h1, l0, l1;
    split2(v.x, v.y, h0, l0);
    split2(v.z, v.w, h1, l1);
    ((uint2*)&g_bfh[mat][row][0])[lid] = make_uint2(h0, h1);
    ((uint2*)&g_bfl[mat][row][0])[lid] = make_uint2(l0, l1);

    // targets + reduction init (first 16 blocks cover 4096)
    int t = blockIdx.x * 256 + tid;
    if (t < N) {
        bool is64 = true;
        #pragma unroll
        for (int j = 0; j < 32; j++)
            if (tgt_raw[2 * j + 1] != 0u) is64 = false;
        g_t[t] = is64 ? (int)tgt_raw[2 * t] : (int)tgt_raw[t];
        const unsigned kap = fkey(-1e30f), kan = fkey(1e30f);
        #pragma unroll
        for (int c = 0; c < 4; c++) {
            g_apu[c][t] = kap;
            g_anu[c][t] = kan;
        }
    }
}

// ---------------------------------------------------------------------------
// tile copy: global row-major [128][128]bf16 -> smem padded rows (cp.async)
// ---------------------------------------------------------------------------
__device__ __forceinline__ void copy_tile(uint32_t dst, const __nv_bfloat16* src,
                                          int tid) {
    const uint4* s = (const uint4*)src;
    #pragma unroll
    for (int j = 0; j < 8; j++) {
        int i = tid + j * 256;
        int row = i >> 4, c = i & 15;
        cpasync16(dst + row * RB + c * 16, s + i);
    }
}

// ---------------------------------------------------------------------------
// main fused kernel, work-list version.
// chunks: c<128 -> rt combo (full 32x32, col side feeds tr);
//         else  -> symmetric combos 0/1, upper-triangular tiles, col side
//                  feeds the same combo via transpose.
// ---------------------------------------------------------------------------
__global__ void __launch_bounds__(256, 1)
dist_mma_kernel() {
    extern __shared__ char smem[];
    const uint32_t sb = smem_u32(smem);
    const int tid = threadIdx.x, wid = tid >> 5, lid = tid & 31;

    // ---- work decode ----
    int combo, col_combo, rb, kb_lo, kb_hi;
    {
        int c = blockIdx.x;
        if (c < 128) {
            combo = 2; col_combo = 3;
            rb = c >> 2;
            kb_lo = (c & 3) * 8;
            kb_hi = kb_lo + 8;
        } else {
            int s = c - 128;
            combo = 0;
            if (s >= 80) { combo = 1; s -= 80; }
            col_combo = combo;
            int rbv = 0, jv = 0, s2 = s;
            #pragma unroll 1
            for (int r = 0; r < 32; r++) {
                int nch = 4 - (r >> 3);
                if (s2 < nch) { rbv = r; jv = (r >> 3) + s2; break; }
                s2 -= nch;
            }
            rb = rbv;
            kb_lo = max(rb, jv * 8);
            kb_hi = jv * 8 + 8;
        }
    }
    const int qsi = (combo == 1) ? 1 : 0;
    const int ksi = (combo == 0) ? 0 : 1;

    const int wm = wid & 1;             // M half (64 rows)
    const int wn = wid >> 1;            // N quarter (32 cols)
    const int g4 = lid >> 2, q4 = lid & 3;
    const int lg = lid >> 3, lr = lid & 7;

    float* s_msq = (float*)(smem + SMEM_MSQ);
    int*   s_mt  = (int*)(smem + SMEM_MT);
    float* s_rap = (float*)(smem + SMEM_RAP);
    float* s_ran = (float*)(smem + SMEM_RAN);

    // ---- prologue: A hi/lo + B(kb_lo) hi/lo + meta0 ----
    copy_tile(sb + SMEM_AH, &g_bfh[qsi][rb * TM][0], tid);
    copy_tile(sb + SMEM_AL, &g_bfl[qsi][rb * TM][0], tid);
    copy_tile(sb + SMEM_B,           &g_bfh[ksi][kb_lo * TN][0], tid);
    copy_tile(sb + SMEM_B + A_BYTES, &g_bfl[ksi][kb_lo * TN][0], tid);
    if (tid < 32)
        cpasync16(sb + SMEM_MSQ + tid * 16,
                  (const char*)&g_sq[ksi][kb_lo * TN] + tid * 16);
    else if (tid < 64)
        cpasync16(sb + SMEM_MT + (tid - 32) * 16,
                  (const char*)&g_t[kb_lo * TN] + (tid - 32) * 16);
    CP_COMMIT();

    // per-thread row metadata
    float sqa[4][2]; int ta[4][2];
    #pragma unroll
    for (int mf = 0; mf < 4; mf++)
        #pragma unroll
        for (int h = 0; h < 2; h++) {
            int r = rb * TM + wm * 64 + mf * 16 + g4 + h * 8;
            sqa[mf][h] = g_sq[qsi][r];
            ta[mf][h]  = g_t[r];
        }

    float ap[8], an[8];
    #pragma unroll
    for (int s = 0; s < 8; s++) { ap[s] = -1e30f; an[s] = 1e30f; }

    float acc[4][4][4];
    #pragma unroll
    for (int mf = 0; mf < 4; mf++)
        #pragma unroll
        for (int nf = 0; nf < 4; nf++)
            #pragma unroll
            for (int e = 0; e < 4; e++) acc[mf][nf][e] = 0.f;

    CP_WAIT0();
    __syncthreads();

    for (int kb = kb_lo; kb < kb_hi; kb++) {
        const int cb = (kb - kb_lo) & 1;

        if (kb + 1 < kb_hi) {
            const int nb = 1 - cb;
            copy_tile(sb + SMEM_B + nb * BBUF,
                      &g_bfh[ksi][(kb + 1) * TN][0], tid);
            copy_tile(sb + SMEM_B + nb * BBUF + A_BYTES,
                      &g_bfl[ksi][(kb + 1) * TN][0], tid);
            if (tid < 32)
                cpasync16(sb + SMEM_MSQ + nb * 512 + tid * 16,
                          (const char*)&g_sq[ksi][(kb + 1) * TN] + tid * 16);
            else if (tid < 64)
                cpasync16(sb + SMEM_MT + nb * 512 + (tid - 32) * 16,
                          (const char*)&g_t[(kb + 1) * TN] + (tid - 32) * 16);
        }
        CP_COMMIT();

        const uint32_t bH = sb + SMEM_B + cb * BBUF;
        const uint32_t bL = bH + A_BYTES;

        for (int ks = 0; ks < 8; ks++) {
            uint32_t Ah[4][4], Al[4][4];
            #pragma unroll
            for (int mf = 0; mf < 4; mf++) {
                int mrow = wm * 64 + mf * 16 + (lg & 1) * 8 + lr;
                int kcol = ks * 16 + (lg >> 1) * 8;
                uint32_t off = (uint32_t)(mrow * RS + kcol) * 2;
                ldsm4(sb + SMEM_AH + off, Ah[mf]);
                ldsm4(sb + SMEM_AL + off, Al[mf]);
            }
            uint32_t Bh[2][4], Bl[2][4];
            #pragma unroll
            for (int ph = 0; ph < 2; ph++) {
                int nrow = wn * 32 + ph * 16 + (lg >> 1) * 8 + lr;
                int kcol = ks * 16 + (lg & 1) * 8;
                uint32_t off = (uint32_t)(nrow * RS + kcol) * 2;
                ldsm4(bH + off, Bh[ph]);
                ldsm4(bL + off, Bl[ph]);
            }
            #pragma unroll
            for (int mf = 0; mf < 4; mf++)
                #pragma unroll
                for (int nf = 0; nf < 4; nf++) {
                    const int ph = nf >> 1, sub = nf & 1;
                    mma_bf16(acc[mf][nf], Ah[mf], Bh[ph][2 * sub], Bh[ph][2 * sub + 1]);
                    mma_bf16(acc[mf][nf], Ah[mf], Bl[ph][2 * sub], Bl[ph][2 * sub + 1]);
                    mma_bf16(acc[mf][nf], Al[mf], Bh[ph][2 * sub], Bh[ph][2 * sub + 1]);
                }
        }

        // ---- epilogue: row-side accumulate + col-side (transpose) ----
        const bool do_col = (combo == 2) || (kb != rb);
        float apc[4][2], anc[4][2];
        #pragma unroll
        for (int nf = 0; nf < 4; nf++)
            #pragma unroll
            for (int par = 0; par < 2; par++) {
                apc[nf][par] = -1e30f;
                anc[nf][par] = 1e30f;
            }

        #pragma unroll
        for (int nf = 0; nf < 4; nf++) {
            const int c0 = wn * 32 + nf * 8 + 2 * q4;
            const float sqb0 = s_msq[cb * 128 + c0];
            const float sqb1 = s_msq[cb * 128 + c0 + 1];
            const int   tb0  = s_mt[cb * 128 + c0];
            const int   tb1  = s_mt[cb * 128 + c0 + 1];
            #pragma unroll
            for (int mf = 0; mf < 4; mf++) {
                #pragma unroll
                for (int h = 0; h < 2; h++) {
                    const int s = mf * 2 + h;
                    float v0 = fmaf(acc[mf][nf][2 * h],     -2.f, sqa[mf][h] + sqb0);
                    float v1 = fmaf(acc[mf][nf][2 * h + 1], -2.f, sqa[mf][h] + sqb1);
                    if (ta[mf][h] == tb0) {
                        ap[s] = fmaxf(ap[s], v0);
                        apc[nf][0] = fmaxf(apc[nf][0], v0);
                    } else {
                        an[s] = fminf(an[s], v0);
                        anc[nf][0] = fminf(anc[nf][0], v0);
                    }
                    if (ta[mf][h] == tb1) {
                        ap[s] = fmaxf(ap[s], v1);
                        apc[nf][1] = fmaxf(apc[nf][1], v1);
                    } else {
                        an[s] = fminf(an[s], v1);
                        anc[nf][1] = fminf(anc[nf][1], v1);
                    }
                    acc[mf][nf][2 * h] = 0.f;
                    acc[mf][nf][2 * h + 1] = 0.f;
                }
            }
        }

        if (do_col) {
            #pragma unroll
            for (int nf = 0; nf < 4; nf++)
                #pragma unroll
                for (int par = 0; par < 2; par++) {
                    #pragma unroll
                    for (int m = 4; m < 32; m <<= 1) {
                        apc[nf][par] = fmaxf(apc[nf][par],
                            __shfl_xor_sync(0xffffffffu, apc[nf][par], m));
                        anc[nf][par] = fminf(anc[nf][par],
                            __shfl_xor_sync(0xffffffffu, anc[nf][par], m));
                    }
                }
            if (lid < 4) {
                #pragma unroll
                for (int nf = 0; nf < 4; nf++)
                    #pragma unroll
                    for (int par = 0; par < 2; par++) {
                        int j = kb * TN + wn * 32 + nf * 8 + 2 * lid + par;
                        atomicMax(&g_apu[col_combo][j], fkey(apc[nf][par]));
                        atomicMin(&g_anu[col_combo][j], fkey(anc[nf][par]));
                    }
            }
        }

        CP_WAIT0();
        __syncthreads();
    }

    // ---- row-side final reduce + atomics ----
    #pragma unroll
    for (int s = 0; s < 8; s++) {
        #pragma unroll
        for (int m = 1; m < 4; m <<= 1) {
            ap[s] = fmaxf(ap[s], __shfl_xor_sync(0xffffffffu, ap[s], m));
            an[s] = fminf(an[s], __shfl_xor_sync(0xffffffffu, an[s], m));
        }
    }
    if (q4 == 0) {
        #pragma unroll
        for (int mf = 0; mf < 4; mf++)
            #pragma unroll
            for (int h = 0; h < 2; h++) {
                int row = wm * 64 + mf * 16 + g4 + h * 8;
                s_rap[wn * 128 + row] = ap[mf * 2 + h];
                s_ran[wn * 128 + row] = an[mf * 2 + h];
            }
    }
    __syncthreads();
    if (tid < 128) {
        float p = s_rap[tid], q = s_ran[tid];
        #pragma unroll
        for (int w = 1; w < 4; w++) {
            p = fmaxf(p, s_rap[w * 128 + tid]);
            q = fminf(q, s_ran[w * 128 + tid]);
        }
        atomicMax(&g_apu[combo][rb * TM + tid], fkey(p));
        atomicMin(&g_anu[combo][rb * TM + tid], fkey(q));
    }
}

// ---------------------------------------------------------------------------
// finalize: stage 1 (16 blocks, 1 row/thread) + stage 2 (combine)
// pairs: (ap1,an1)(ap2,an2)(ap3,an3)(ap4,an4)(ap3,an1)(ap4,an2)
// ---------------------------------------------------------------------------
__global__ void finalize1_kernel() {
    __shared__ float sl[256];
    __shared__ float sp[256];
    const int tid = threadIdx.x;
    const int i = blockIdx.x * 256 + tid;
    const int pi[6] = {0, 1, 2, 3, 2, 3};
    const int ni[6] = {0, 1, 2, 3, 0, 1};
    float A[4], B[4];
    #pragma unroll
    for (int c = 0; c < 4; c++) {
        A[c] = sqrtf(fmaxf(funkey(g_apu[c][i]), 1e-12f));
        B[c] = sqrtf(fmaxf(funkey(g_anu[c][i]), 1e-12f));
    }
    float lsum = 0.f, psum = 0.f;
    #pragma unroll
    for (int j = 0; j < 6; j++) {
        float apv = A[pi[j]], anv = B[ni[j]];
        lsum += fmaxf(apv - anv + 0.3f, 0.f);
        psum += (anv > apv) ? 1.f : 0.f;
    }
    sl[tid] = lsum; sp[tid] = psum;
    __syncthreads();
    for (int s = 128; s > 0; s >>= 1) {
        if (tid < s) { sl[tid] += sl[tid + s]; sp[tid] += sp[tid + s]; }
        __syncthreads();
    }
    if (tid == 0) {
        g_part[blockIdx.x][0] = sl[0];
        g_part[blockIdx.x][1] = sp[0];
    }
}

__global__ void finalize2_kernel(float* __restrict__ out, int out_size) {
    const int tid = threadIdx.x;
    float l = 0.f, p = 0.f;
    if (tid < 16) { l = g_part[tid][0]; p = g_part[tid][1]; }
    #pragma unroll
    for (int m = 8; m; m >>= 1) {
        l += __shfl_xor_sync(0xffffffffu, l, m);
        p += __shfl_xor_sync(0xffffffffu, p, m);
    }
    if (tid == 0) {
        const float inv = 1.f / (6.f * (float)N);
        if (out_size > 0) out[0] = l * inv;
        if (out_size > 1) out[1] = p * inv;
    }
}

// ---------------------------------------------------------------------------
extern "C" void kernel_launch(void* const* d_in, const int* in_sizes, int n_in,
                              void* d_out, int out_size) {
    const float* m1 = (const float*)d_in[0];
    const float* m2 = (const float*)d_in[1];
    const unsigned int* tgt = (const unsigned int*)d_in[2];
    float* out = (float*)d_out;

    cudaFuncSetAttribute(dist_mma_kernel,
                         cudaFuncAttributeMaxDynamicSharedMemorySize, SMEM_TOT);

    prep2_kernel<<<1024, 256>>>(m1, m2, tgt);
    dist_mma_kernel<<<NCTA, 256, SMEM_TOT>>>();
    finalize1_kernel<<<16, 256>>>();
    finalize2_kernel<<<1, 32>>>(out, out_size);
}